// round 12
// baseline (speedup 1.0000x reference)
#include <cuda_runtime.h>

// RandomShiftsAug on GB300 — integer-shift copy with edge clamp.
// out[n,c,y,x] = in[n,c, clamp(y+sy-4,0,127), clamp(x+sx-4,0,127)]
//
// R12: R11 shuffle scheme + intra-warp software pipeline.
//  Warp owns 8 rows of one (n,c) image, processed as 4 steps x 2 rows with a
//  depth-2 register double buffer: loads of step t+1 are issued BEFORE the
//  shfl+store of step t, so the warp keeps loads in flight continuously
//  (R11 front-loads 4 LDGs then never loads again -> bursty read stream).
//  No smem, no barriers; per 512B row: 4 LDG.128 + 4 STG.128 wavefronts.

#define PADV 4
#define CB   9
#define HB   128
#define FULLM 0xFFFFFFFFu

__global__ void __launch_bounds__(256)
random_shift_pipe_kernel(const float* __restrict__ x,
                         const int* __restrict__ shift,
                         float* __restrict__ out)
{
    int w = threadIdx.x >> 5;
    int l = threadIdx.x & 31;

    int gwarp = blockIdx.x * 8 + w;    // 73728 warps
    int seg   = gwarp & 15;            // 16 row-octets per image
    int nc    = gwarp >> 4;            // n*9 + c
    int y0    = seg << 3;
    int n     = nc / CB;

    int sx = shift[2 * n]     - PADV;  // warp-uniform, in [-4,4]
    int sy = shift[2 * n + 1] - PADV;

    const float4* __restrict__ img4 =
        reinterpret_cast<const float4*>(x) + nc * (HB * HB / 4);

    int c0 = (l << 2) + sx;            // first source col of my output quad
    int q0 = c0 >> 2;
    int qa = q0 < 0 ? 0 : (q0 > 31 ? 31 : q0);
    int qb = q0 + 1 > 31 ? 31 : q0 + 1;
    int rot = sx & 3;                  // warp-uniform

    float4* __restrict__ dst4 =
        reinterpret_cast<float4*>(out) + (nc * HB + y0) * (HB / 4) + l;

    float4 B[2][2];

    // load 2 source rows for output rows [yb, yb+1]
    #define LOAD2(buf, yb)                                                  \
        {                                                                   \
            _Pragma("unroll")                                               \
            for (int r = 0; r < 2; r++) {                                   \
                int ys = (yb) + r + sy;                                     \
                ys = ys < 0 ? 0 : (ys > HB - 1 ? HB - 1 : ys);              \
                (buf)[r] = __ldcs(img4 + ys * (HB / 4) + l);                \
            }                                                               \
        }

    LOAD2(B[0], y0);                   // prologue

    #pragma unroll
    for (int t = 0; t < 4; t++) {
        if (t < 3) LOAD2(B[(t + 1) & 1], y0 + 2 * (t + 1));  // prefetch next

        #pragma unroll
        for (int r = 0; r < 2; r++) {
            float4 a = B[t & 1][r];
            float o0, o1, o2, o3;
            switch (rot) {             // warp-uniform branch
            case 0:
                o0 = __shfl_sync(FULLM, a.x, qa); o1 = __shfl_sync(FULLM, a.y, qa);
                o2 = __shfl_sync(FULLM, a.z, qa); o3 = __shfl_sync(FULLM, a.w, qa);
                break;
            case 1:
                o0 = __shfl_sync(FULLM, a.y, qa); o1 = __shfl_sync(FULLM, a.z, qa);
                o2 = __shfl_sync(FULLM, a.w, qa); o3 = __shfl_sync(FULLM, a.x, qb);
                break;
            case 2:
                o0 = __shfl_sync(FULLM, a.z, qa); o1 = __shfl_sync(FULLM, a.w, qa);
                o2 = __shfl_sync(FULLM, a.x, qb); o3 = __shfl_sync(FULLM, a.y, qb);
                break;
            default:
                o0 = __shfl_sync(FULLM, a.w, qa); o1 = __shfl_sync(FULLM, a.x, qb);
                o2 = __shfl_sync(FULLM, a.y, qb); o3 = __shfl_sync(FULLM, a.z, qb);
                break;
            }

            float first = __shfl_sync(FULLM, a.x, 0);    // col 0
            float last  = __shfl_sync(FULLM, a.w, 31);   // col 127

            if (c0     < 0) o0 = first; else if (c0     > HB - 1) o0 = last;
            if (c0 + 1 < 0) o1 = first; else if (c0 + 1 > HB - 1) o1 = last;
            if (c0 + 2 < 0) o2 = first; else if (c0 + 2 > HB - 1) o2 = last;
            if (c0 + 3 < 0) o3 = first; else if (c0 + 3 > HB - 1) o3 = last;

            float4 v; v.x = o0; v.y = o1; v.z = o2; v.w = o3;
            __stcs(dst4 + (2 * t + r) * (HB / 4), v);
        }
    }
    #undef LOAD2
}

extern "C" void kernel_launch(void* const* d_in, const int* in_sizes, int n_in,
                              void* d_out, int out_size)
{
    const float* x     = (const float*)d_in[0];
    const int*   shift = (const int*)d_in[1];
    float*       out   = (float*)d_out;

    // 4608 images * 16 row-octets = 73728 warps / 8 per CTA = 9216 CTAs
    random_shift_pipe_kernel<<<9216, 256>>>(x, shift, out);
}

// round 15
// speedup vs baseline: 1.0192x; 1.0192x over previous
#include <cuda_runtime.h>

// RandomShiftsAug on GB300 — integer-shift copy with edge clamp.
// out[n,c,y,x] = in[n,c, clamp(y+sy-4,0,127), clamp(x+sx-4,0,127)]
//
// R13 = R11 (best: register+shuffle, no smem, no barriers, MLP=4) plus:
//  - ld.global.cs.L2::256B prefetch hint on row loads (rows consumed
//    sequentially -> wider L2 fetch granularity is never wasted),
//  - warp-uniform guards on the edge-clamp path (first/last shfls + selects
//    only execute when sx<0 / sx>0).

#define PADV 4
#define CB   9
#define HB   128
#define RW   4
#define FULLM 0xFFFFFFFFu

__device__ __forceinline__ float4 ldcs_256(const float4* p)
{
    float4 v;
    asm volatile("ld.global.cs.L2::256B.v4.f32 {%0,%1,%2,%3}, [%4];"
                 : "=f"(v.x), "=f"(v.y), "=f"(v.z), "=f"(v.w)
                 : "l"(p));
    return v;
}

__global__ void __launch_bounds__(256)
random_shift_shfl2_kernel(const float* __restrict__ x,
                          const int* __restrict__ shift,
                          float* __restrict__ out)
{
    int w = threadIdx.x >> 5;
    int l = threadIdx.x & 31;

    int gwarp = blockIdx.x * 8 + w;    // 147456 warps
    int grp   = gwarp & 31;            // 32 row-quartets per image
    int nc    = gwarp >> 5;            // n*9 + c
    int y0    = grp << 2;
    int n     = nc / CB;

    int sx = shift[2 * n]     - PADV;  // warp-uniform, in [-4,4]
    int sy = shift[2 * n + 1] - PADV;

    const float4* __restrict__ img4 =
        reinterpret_cast<const float4*>(x) + nc * (HB * HB / 4);

    // ---- 4 aligned LDG.128 in flight (with 256B L2 prefetch hint) ----
    float4 A[RW];
    #pragma unroll
    for (int r = 0; r < RW; r++) {
        int ys = y0 + r + sy;
        ys = ys < 0 ? 0 : (ys > HB - 1 ? HB - 1 : ys);
        A[r] = ldcs_256(img4 + ys * (HB / 4) + l);
    }

    int c0 = (l << 2) + sx;            // first source col of my output quad
    int q0 = c0 >> 2;
    int qa = q0 < 0 ? 0 : (q0 > 31 ? 31 : q0);
    int qb = q0 + 1 > 31 ? 31 : q0 + 1;
    int rot = sx & 3;                  // warp-uniform

    float4* __restrict__ dst4 =
        reinterpret_cast<float4*>(out) + (nc * HB + y0) * (HB / 4) + l;

    #pragma unroll
    for (int r = 0; r < RW; r++) {
        float4 a = A[r];
        float o0, o1, o2, o3;
        switch (rot) {                 // warp-uniform branch
        case 0:
            o0 = __shfl_sync(FULLM, a.x, qa); o1 = __shfl_sync(FULLM, a.y, qa);
            o2 = __shfl_sync(FULLM, a.z, qa); o3 = __shfl_sync(FULLM, a.w, qa);
            break;
        case 1:
            o0 = __shfl_sync(FULLM, a.y, qa); o1 = __shfl_sync(FULLM, a.z, qa);
            o2 = __shfl_sync(FULLM, a.w, qa); o3 = __shfl_sync(FULLM, a.x, qb);
            break;
        case 2:
            o0 = __shfl_sync(FULLM, a.z, qa); o1 = __shfl_sync(FULLM, a.w, qa);
            o2 = __shfl_sync(FULLM, a.x, qb); o3 = __shfl_sync(FULLM, a.y, qb);
            break;
        default:
            o0 = __shfl_sync(FULLM, a.w, qa); o1 = __shfl_sync(FULLM, a.x, qb);
            o2 = __shfl_sync(FULLM, a.y, qb); o3 = __shfl_sync(FULLM, a.z, qb);
            break;
        }

        // Edge clamp — warp-uniform guarded (shfls are warp-wide inside).
        if (sx < 0) {                  // only left edge (lane 0) can clamp low
            float first = __shfl_sync(FULLM, a.x, 0);    // col 0
            if (c0     < 0) o0 = first;
            if (c0 + 1 < 0) o1 = first;
            if (c0 + 2 < 0) o2 = first;
            if (c0 + 3 < 0) o3 = first;
        } else if (sx > 0) {           // only right edge (lane 31) can clamp high
            float last = __shfl_sync(FULLM, a.w, 31);    // col 127
            if (c0     > HB - 1) o0 = last;
            if (c0 + 1 > HB - 1) o1 = last;
            if (c0 + 2 > HB - 1) o2 = last;
            if (c0 + 3 > HB - 1) o3 = last;
        }

        float4 v; v.x = o0; v.y = o1; v.z = o2; v.w = o3;
        __stcs(dst4 + r * (HB / 4), v);
    }
}

extern "C" void kernel_launch(void* const* d_in, const int* in_sizes, int n_in,
                              void* d_out, int out_size)
{
    const float* x     = (const float*)d_in[0];
    const int*   shift = (const int*)d_in[1];
    float*       out   = (float*)d_out;

    // 4608 images * 32 row-quartets = 147456 warps / 8 per CTA = 18432 CTAs
    random_shift_shfl2_kernel<<<18432, 256>>>(x, shift, out);
}